// round 4
// baseline (speedup 1.0000x reference)
#include <cuda_runtime.h>
#include <math.h>

#define BB 2
#define NN 512
#define SS 384
#define ZC 128
#define HH 12
#define CC 16
#define PQn 4
#define PVn 8
#define HC 192      /* H*C   */
#define HPQ3 144    /* H*PQ*3*/
#define HPV3 288    /* H*PV*3*/
#define CATW 2112   /* H*(C+4PV+Z) */
#define PROJ_W 1152

#define WLC  0.5773502691896258f     /* sqrt(1/3) */
#define COEF 0.06804138174397717f    /* wL*wC/2, wC=sqrt(2/(9*PQ)) */

__device__ __align__(16) float g_q [BB*NN*HC];
__device__ __align__(16) float g_k [BB*NN*HC];
__device__ __align__(16) float g_v [BB*NN*HC];
__device__ __align__(16) float g_qp[BB*NN*HPQ3];
__device__ __align__(16) float g_kp[BB*NN*HPQ3];
__device__ __align__(16) float g_vp[BB*NN*HPV3];
__device__ __align__(16) float g_qq[BB*NN*HH];
__device__ __align__(16) float g_kk[BB*NN*HH];
__device__ __align__(16) float g_cat[BB*NN*CATW];
__device__ __align__(16) float g_wcat[SS*PROJ_W];   // packed projection weights
__device__ __align__(16) float g_proj[BB*NN*PROJ_W];

__device__ __forceinline__ float dot4(float4 a, float4 b) {
    return a.x*b.x + a.y*b.y + a.z*b.z + a.w*b.w;
}

// ---- packed f32x2 helpers (sm_103a; ptxas never auto-fuses these) ----------
__device__ __forceinline__ void ffma2(unsigned long long& acc,
                                      unsigned long long a, unsigned long long b) {
    asm("fma.rn.f32x2 %0, %1, %2, %0;" : "+l"(acc) : "l"(a), "l"(b));
}
__device__ __forceinline__ unsigned long long pack2(float lo, float hi) {
    unsigned long long r;
    asm("mov.b64 %0, {%1, %2};" : "=l"(r) : "f"(lo), "f"(hi));
    return r;
}
__device__ __forceinline__ float hadd2(unsigned long long v) {
    float lo, hi;
    asm("mov.b64 {%0, %1}, %2;" : "=f"(lo), "=f"(hi) : "l"(v));
    return lo + hi;
}

// ---------------------------------------------------------------------------
// Kernel 0: pack Wq|Wk|Wv|Wqp|Wkp|Wvp into g_wcat[384][1152]
// ---------------------------------------------------------------------------
__global__ __launch_bounds__(256) void k_pack(
    const float* __restrict__ Wq, const float* __restrict__ Wk, const float* __restrict__ Wv,
    const float* __restrict__ Wqp, const float* __restrict__ Wkp, const float* __restrict__ Wvp)
{
    const int idx = blockIdx.x*256 + threadIdx.x;
    const int si = idx / PROJ_W, col = idx % PROJ_W;
    float v;
    if      (col < 192) v = Wq [si*192 + col];
    else if (col < 384) v = Wk [si*192 + col - 192];
    else if (col < 576) v = Wv [si*192 + col - 384];
    else if (col < 720) v = Wqp[si*144 + col - 576];
    else if (col < 864) v = Wkp[si*144 + col - 720];
    else                v = Wvp[si*288 + col - 864];
    g_wcat[idx] = v;
}

// ---------------------------------------------------------------------------
// Generic tiled fp32 GEMM: C[M,N] = A[M,lda] @ B[K,ldb], 256 threads.
// ---------------------------------------------------------------------------
template<int BM, int BN, int TM, int TN>
__global__ __launch_bounds__(256) void k_gemm(
    const float* __restrict__ A, int lda,
    const float* __restrict__ B, int ldb,
    float* __restrict__ C, int ldc, int K)
{
    constexpr int BK = 32;
    __shared__ float As[BK][BM + 1];
    __shared__ __align__(16) float Bs[BK][BN];
    const int tid = threadIdx.x;
    const int ncols = BN / TN;
    const int tr = tid / ncols;
    const int tc = tid % ncols;
    const int m0 = blockIdx.y * BM;
    const int n0 = blockIdx.x * BN;

    float acc[TM][TN];
    #pragma unroll
    for (int i = 0; i < TM; i++)
        #pragma unroll
        for (int j = 0; j < TN; j++) acc[i][j] = 0.f;

    for (int k0 = 0; k0 < K; k0 += BK) {
        #pragma unroll
        for (int r = 0; r < (BM*BK)/256; r++) {
            const int idx = tid + r*256;
            const int m = idx / BK, kk = idx % BK;
            As[kk][m] = A[(m0 + m)*lda + k0 + kk];
        }
        #pragma unroll
        for (int r = 0; r < (BN*BK)/256; r++) {
            const int idx = tid + r*256;
            const int kk = idx / BN, n = idx % BN;
            Bs[kk][n] = B[(k0 + kk)*ldb + n0 + n];
        }
        __syncthreads();
        #pragma unroll
        for (int kk = 0; kk < BK; kk++) {
            float a[TM];
            #pragma unroll
            for (int i = 0; i < TM; i++) a[i] = As[kk][tr*TM + i];
            const float4 b4 = *(const float4*)&Bs[kk][tc*TN];
            #pragma unroll
            for (int i = 0; i < TM; i++) {
                acc[i][0] = fmaf(a[i], b4.x, acc[i][0]);
                acc[i][1] = fmaf(a[i], b4.y, acc[i][1]);
                acc[i][2] = fmaf(a[i], b4.z, acc[i][2]);
                acc[i][3] = fmaf(a[i], b4.w, acc[i][3]);
            }
        }
        __syncthreads();
    }
    #pragma unroll
    for (int i = 0; i < TM; i++) {
        float4 v = make_float4(acc[i][0], acc[i][1], acc[i][2], acc[i][3]);
        *(float4*)&C[(m0 + tr*TM + i)*ldc + n0 + tc*TN] = v;
    }
}

// ---------------------------------------------------------------------------
// Kernel: post-projection epilogue. One block per (b,n) residue.
// ---------------------------------------------------------------------------
__global__ __launch_bounds__(128) void k_projpost(
    const float* __restrict__ R, const float* __restrict__ t)
{
    __shared__ float qq_sh[HH], kk_sh[HH];
    __shared__ float Rl[9], tl[3];
    const int bn  = blockIdx.x;
    const int tid = threadIdx.x;
    const float* proj = g_proj + bn*PROJ_W;

    if (tid < HH) { qq_sh[tid] = 0.f; kk_sh[tid] = 0.f; }
    if (tid < 9)  Rl[tid] = R[bn*9 + tid];
    if (tid < 3)  tl[tid] = t[bn*3 + tid];
    __syncthreads();

    for (int i = tid; i < HC; i += 128) {
        g_q[bn*HC + i] = proj[i];
        g_k[bn*HC + i] = proj[192 + i];
        g_v[bn*HC + i] = proj[384 + i];
    }
    if (tid < 96) {
        const int which = tid / 48;
        const int pt    = tid % 48;
        const int off   = which ? 720 : 576;
        const float px = proj[off + pt*3], py = proj[off + pt*3 + 1], pz = proj[off + pt*3 + 2];
        const float gx = Rl[0]*px + Rl[1]*py + Rl[2]*pz + tl[0];
        const float gy = Rl[3]*px + Rl[4]*py + Rl[5]*pz + tl[1];
        const float gz = Rl[6]*px + Rl[7]*py + Rl[8]*pz + tl[2];
        float* dst = (which ? g_kp : g_qp) + bn*HPQ3 + pt*3;
        dst[0] = gx; dst[1] = gy; dst[2] = gz;
        atomicAdd((which ? kk_sh : qq_sh) + pt/PQn, gx*gx + gy*gy + gz*gz);
    }
    if (tid < 96) {
        const int pt = tid;
        const float px = proj[864 + pt*3], py = proj[864 + pt*3 + 1], pz = proj[864 + pt*3 + 2];
        float* dst = g_vp + bn*HPV3 + pt*3;
        dst[0] = Rl[0]*px + Rl[1]*py + Rl[2]*pz + tl[0];
        dst[1] = Rl[3]*px + Rl[4]*py + Rl[5]*pz + tl[1];
        dst[2] = Rl[6]*px + Rl[7]*py + Rl[8]*pz + tl[2];
    }
    __syncthreads();
    if (tid < HH) { g_qq[bn*HH + tid] = qq_sh[tid]; g_kk[bn*HH + tid] = kk_sh[tid]; }
}

// ---------------------------------------------------------------------------
// Kernel: fused bias + logits + softmax + (o, opt, norm, opair) -> g_cat.
// One block = 4 query rows, 512 threads, occupancy 1 (min-blocks=2 spills!).
// ---------------------------------------------------------------------------
#define L_LOGITS 0                 /* 4*12*512 = 24576 */
#define L_WBT    24576             /* 12*128   =  1536 ; aliased by og_s */
#define L_QS     26112             /* 4*192    =   768 */
#define L_QPS    26880             /* 4*192    =   768 */
#define L_QQS    27648             /* 48 */
#define L_GM     27696             /* 12 */
#define L_RS     27708             /* 36 */
#define L_TS     27744             /* 12 */
#define ATTN_SMEM_FLOATS 27756
#define ATTN_SMEM_BYTES  (ATTN_SMEM_FLOATS*4)

__global__ __launch_bounds__(512) void k_attn(
    const float* __restrict__ z, const float* __restrict__ Wb,
    const float* __restrict__ hw, const float* __restrict__ R,
    const float* __restrict__ t)
{
    extern __shared__ __align__(16) float sm[];
    float* logits = sm + L_LOGITS;
    float* wbT    = sm + L_WBT;
    float* og_s   = sm + L_WBT;      // alias: wbT dead after phase 1a
    float* q_s    = sm + L_QS;
    float* qp_s   = sm + L_QPS;
    float* qq_s   = sm + L_QQS;
    float* gm     = sm + L_GM;
    float* R_s    = sm + L_RS;
    float* t_s    = sm + L_TS;

    const int tid = threadIdx.x;
    const int blk = blockIdx.x;
    const int b   = blk >> 7;            // 128 blocks per batch
    const int i0  = (blk & 127) << 2;    // 4 query rows per block

    // ---- setup ----
    for (int idx = tid; idx < HH*ZC; idx += 512) {
        const int h = idx / ZC, zi = idx % ZC;
        wbT[h*ZC + zi] = Wb[zi*HH + h];
    }
    for (int idx = tid; idx < 4*HC; idx += 512) {
        const int il = idx / HC;
        q_s[idx] = g_q[(b*NN + i0 + il)*HC + (idx % HC)];
    }
    for (int idx = tid; idx < 4*HPQ3; idx += 512) {
        const int il = idx / HPQ3, r = idx % HPQ3;
        const int h = r / 12, d = r % 12;
        qp_s[il*192 + h*16 + d] = g_qp[(b*NN + i0 + il)*HPQ3 + r];
    }
    if (tid < 48) qq_s[tid] = g_qq[(b*NN + i0 + tid/12)*HH + tid%12];
    if (tid < HH) gm[tid]   = log1pf(expf(hw[tid]));          // softplus
    if (tid < 36) R_s[tid]  = R[(b*NN + i0 + tid/9)*9 + tid%9];
    if (tid < 12) t_s[tid]  = t[(b*NN + i0 + tid/3)*3 + tid%3];
    __syncthreads();

    const int j = tid;   // this thread's key index

    // ---- phase 1a: pair bias (z @ Wb), f32x2 packed along z-channels ----
    for (int il = 0; il < 4; il++) {
        unsigned long long acc2[HH];
        #pragma unroll
        for (int h = 0; h < HH; h++) acc2[h] = 0ull;
        const ulonglong2* zr = (const ulonglong2*)(z + ((size_t)(b*NN + i0 + il)*NN + j)*ZC);
        #pragma unroll 4
        for (int c4 = 0; c4 < ZC/4; c4++) {
            const ulonglong2 zv = zr[c4];
            #pragma unroll
            for (int h = 0; h < HH; h++) {
                const ulonglong2 wv = *(const ulonglong2*)(wbT + h*ZC + c4*4);
                ffma2(acc2[h], zv.x, wv.x);
                ffma2(acc2[h], zv.y, wv.y);
            }
        }
        #pragma unroll
        for (int h = 0; h < HH; h++) logits[(il*HH + h)*NN + j] = hadd2(acc2[h]);
    }

    // ---- phase 1b: scalar + point logits ----
    {
        const float4* kr  = (const float4*)(g_k  + (b*NN + j)*HC);
        const float4* kpr = (const float4*)(g_kp + (b*NN + j)*HPQ3);
        const float*  kkr = g_kk + (b*NN + j)*HH;
        for (int h = 0; h < HH; h++) {
            const float4 kv0 = kr[h*4+0], kv1 = kr[h*4+1], kv2 = kr[h*4+2], kv3 = kr[h*4+3];
            const float4 kp0 = kpr[h*3+0], kp1 = kpr[h*3+1], kp2 = kpr[h*3+2];
            const float  kkh = kkr[h];
            const float  gch = COEF * gm[h];
            #pragma unroll
            for (int il = 0; il < 4; il++) {
                const float4* qh  = (const float4*)(q_s  + il*192 + h*16);
                const float4* qph = (const float4*)(qp_s + il*192 + h*16);
                float sc = dot4(qh[0],kv0) + dot4(qh[1],kv1) + dot4(qh[2],kv2) + dot4(qh[3],kv3);
                float qk = dot4(qph[0],kp0) + dot4(qph[1],kp1) + dot4(qph[2],kp2);
                const float d2 = qq_s[il*HH + h] + kkh - 2.f*qk;
                const int   li = (il*HH + h)*NN + j;
                logits[li] = WLC*(sc*0.25f + logits[li]) - gch*d2;
            }
        }
    }
    __syncthreads();

    // ---- phase 2: softmax over j, one warp per (il,h) row ----
    {
        const int wid = tid >> 5, lane = tid & 31;
        for (int row = wid; row < 48; row += 16) {
            float* Lr = logits + row*NN;
            float m = -1e30f;
            for (int c = lane; c < NN; c += 32) m = fmaxf(m, Lr[c]);
            #pragma unroll
            for (int o = 16; o; o >>= 1) m = fmaxf(m, __shfl_xor_sync(0xffffffffu, m, o));
            float ssum = 0.f;
            for (int c = lane; c < NN; c += 32) { const float e = __expf(Lr[c] - m); Lr[c] = e; ssum += e; }
            #pragma unroll
            for (int o = 16; o; o >>= 1) ssum += __shfl_xor_sync(0xffffffffu, ssum, o);
            const float inv = 1.f / ssum;
            for (int c = lane; c < NN; c += 32) Lr[c] *= inv;
        }
    }
    __syncthreads();

    // ---- phase 3a: opair = a @ z, f32x2 packed along j ----
    {
        const int il  = tid >> 7;
        const int col = tid & 127;
        unsigned long long acc2[HH];
        #pragma unroll
        for (int h = 0; h < HH; h++) acc2[h] = 0ull;
        const float* zcol = z + ((size_t)(b*NN + i0 + il)*NN)*ZC + col;
        const float* arow = logits + il*HH*NN;
        #pragma unroll 2
        for (int jj = 0; jj < NN; jj += 4) {
            const float z0 = zcol[(size_t)(jj+0)*ZC];
            const float z1 = zcol[(size_t)(jj+1)*ZC];
            const float z2 = zcol[(size_t)(jj+2)*ZC];
            const float z3 = zcol[(size_t)(jj+3)*ZC];
            const unsigned long long zp0 = pack2(z0, z1);
            const unsigned long long zp1 = pack2(z2, z3);
            #pragma unroll
            for (int h = 0; h < HH; h++) {
                const ulonglong2 av = *(const ulonglong2*)(arow + h*NN + jj);
                ffma2(acc2[h], av.x, zp0);
                ffma2(acc2[h], av.y, zp1);
            }
        }
        float* dst = g_cat + (size_t)(b*NN + i0 + il)*CATW + 576 + col;
        #pragma unroll
        for (int h = 0; h < HH; h++) dst[h*ZC] = hadd2(acc2[h]);
    }

    // ---- phase 3bc: o = a@v and opt_g = a@vp, one float4 column per thread --
    // items: il(4) x (48 v-cols4 + 72 vp-cols4) = 480
    if (tid < 480) {
        const int il = tid / 120;
        const int c  = tid % 120;
        const float* src; int ld, h;
        if (c < 48) { src = g_v  + (size_t)b*NN*HC   + c*4;      ld = HC;   h = c >> 2; }
        else        { src = g_vp + (size_t)b*NN*HPV3 + (c-48)*4; ld = HPV3; h = (c-48) / 6; }
        const float* arow = logits + (il*HH + h)*NN;
        float4 acc = make_float4(0.f, 0.f, 0.f, 0.f);
        #pragma unroll 2
        for (int jj4 = 0; jj4 < NN/4; jj4++) {
            const float4 a4 = *(const float4*)(arow + jj4*4);
            const float4 v0 = *(const float4*)(src + (size_t)(jj4*4+0)*ld);
            const float4 v1 = *(const float4*)(src + (size_t)(jj4*4+1)*ld);
            const float4 v2 = *(const float4*)(src + (size_t)(jj4*4+2)*ld);
            const float4 v3 = *(const float4*)(src + (size_t)(jj4*4+3)*ld);
            acc.x = fmaf(a4.x, v0.x, fmaf(a4.y, v1.x, fmaf(a4.z, v2.x, fmaf(a4.w, v3.x, acc.x))));
            acc.y = fmaf(a4.x, v0.y, fmaf(a4.y, v1.y, fmaf(a4.z, v2.y, fmaf(a4.w, v3.y, acc.y))));
            acc.z = fmaf(a4.x, v0.z, fmaf(a4.y, v1.z, fmaf(a4.z, v2.z, fmaf(a4.w, v3.z, acc.z))));
            acc.w = fmaf(a4.x, v0.w, fmaf(a4.y, v1.w, fmaf(a4.z, v2.w, fmaf(a4.w, v3.w, acc.w))));
        }
        if (c < 48) *(float4*)(g_cat + (size_t)(b*NN + i0 + il)*CATW + c*4) = acc;
        else        *(float4*)(og_s + il*HPV3 + (c-48)*4) = acc;
    }
    __syncthreads();

    // ---- phase 3d: back to local frame (R^T (x - t)), + norms ----
    for (int idx = tid; idx < 4*96; idx += 512) {
        const int il = idx / 96, hp = idx % 96;  // hp = h*8 + p
        const float dx = og_s[il*HPV3 + hp*3 + 0] - t_s[il*3 + 0];
        const float dy = og_s[il*HPV3 + hp*3 + 1] - t_s[il*3 + 1];
        const float dz = og_s[il*HPV3 + hp*3 + 2] - t_s[il*3 + 2];
        const float* Rr = R_s + il*9;
        const float ox = Rr[0]*dx + Rr[3]*dy + Rr[6]*dz;
        const float oy = Rr[1]*dx + Rr[4]*dy + Rr[7]*dz;
        const float oz = Rr[2]*dx + Rr[5]*dy + Rr[8]*dz;
        float* cg = g_cat + (size_t)(b*NN + i0 + il)*CATW;
        cg[192 + hp*3 + 0] = ox;
        cg[192 + hp*3 + 1] = oy;
        cg[192 + hp*3 + 2] = oz;
        cg[480 + hp] = sqrtf(ox*ox + oy*oy + oz*oz + 1e-8f);
    }
}

// ---------------------------------------------------------------------------
extern "C" void kernel_launch(void* const* d_in, const int* in_sizes, int n_in,
                              void* d_out, int out_size)
{
    const float* s    = (const float*)d_in[0];
    const float* z    = (const float*)d_in[1];
    const float* R    = (const float*)d_in[2];
    const float* t    = (const float*)d_in[3];
    const float* Wq   = (const float*)d_in[4];
    const float* Wk   = (const float*)d_in[5];
    const float* Wv   = (const float*)d_in[6];
    const float* Wqp  = (const float*)d_in[7];
    const float* Wkp  = (const float*)d_in[8];
    const float* Wvp  = (const float*)d_in[9];
    const float* Wb   = (const float*)d_in[10];
    const float* hw   = (const float*)d_in[11];
    const float* Wout = (const float*)d_in[12];
    float* out = (float*)d_out;

    cudaFuncSetAttribute(k_attn, cudaFuncAttributeMaxDynamicSharedMemorySize, ATTN_SMEM_BYTES);

    float* g_wcat_p;  cudaGetSymbolAddress((void**)&g_wcat_p, g_wcat);
    float* g_proj_p;  cudaGetSymbolAddress((void**)&g_proj_p, g_proj);
    float* g_cat_p;   cudaGetSymbolAddress((void**)&g_cat_p,  g_cat);

    // 1) pack weights, project: g_proj[1024,1152] = s[1024,384] @ g_wcat
    k_pack<<<(SS*PROJ_W)/256, 256>>>(Wq, Wk, Wv, Wqp, Wkp, Wvp);
    {
        dim3 grid(PROJ_W/64, (BB*NN)/64);
        k_gemm<64, 64, 4, 4><<<grid, 256>>>(s, SS, g_wcat_p, PROJ_W, g_proj_p, PROJ_W, SS);
    }
    k_projpost<<<BB*NN, 128>>>(R, t);

    // 2) attention + gather into g_cat
    k_attn<<<BB*(NN/4), 512, ATTN_SMEM_BYTES>>>(z, Wb, hw, R, t);

    // 3) out = g_cat[1024,2112] @ Wout[2112,384]
    {
        dim3 grid(SS/64, (BB*NN)/32);
        k_gemm<32, 64, 2, 4><<<grid, 256>>>(g_cat_p, CATW, Wout, SS, out, SS, CATW);
    }
}

// round 6
// speedup vs baseline: 1.0908x; 1.0908x over previous
#include <cuda_runtime.h>
#include <math.h>

#define BB 2
#define NN 512
#define SS 384
#define ZC 128
#define HH 12
#define CC 16
#define PQn 4
#define PVn 8
#define HC 192      /* H*C   */
#define HPQ3 144    /* H*PQ*3*/
#define HPV3 288    /* H*PV*3*/
#define CATW 2112   /* H*(C+4PV+Z) */
#define PROJ_W 1152

#define WLC  0.5773502691896258f     /* sqrt(1/3) */
#define COEF 0.06804138174397717f    /* wL*wC/2, wC=sqrt(2/(9*PQ)) */

__device__ __align__(16) float g_q [BB*NN*HC];
__device__ __align__(16) float g_k [BB*NN*HC];
__device__ __align__(16) float g_v [BB*NN*HC];
__device__ __align__(16) float g_qp[BB*NN*HPQ3];
__device__ __align__(16) float g_kp[BB*NN*HPQ3];
__device__ __align__(16) float g_vp[BB*NN*HPV3];
__device__ __align__(16) float g_qq[BB*NN*HH];
__device__ __align__(16) float g_kk[BB*NN*HH];
__device__ __align__(16) float g_cat[BB*NN*CATW];
__device__ __align__(16) float g_wcat[SS*PROJ_W];
__device__ __align__(16) float g_proj[BB*NN*PROJ_W];
// bias, then (after k_logits) attention weights; layout [b, i, h, j] (25 MB)
__device__ __align__(16) float g_att[(size_t)BB*NN*HH*NN];

__device__ __forceinline__ float dot4(float4 a, float4 b) {
    return a.x*b.x + a.y*b.y + a.z*b.z + a.w*b.w;
}

// ---- packed f32x2 helpers ---------------------------------------------------
__device__ __forceinline__ void ffma2(unsigned long long& acc,
                                      unsigned long long a, unsigned long long b) {
    asm("fma.rn.f32x2 %0, %1, %2, %0;" : "+l"(acc) : "l"(a), "l"(b));
}
__device__ __forceinline__ unsigned long long pack2(float lo, float hi) {
    unsigned long long r;
    asm("mov.b64 %0, {%1, %2};" : "=l"(r) : "f"(lo), "f"(hi));
    return r;
}
__device__ __forceinline__ float hadd2(unsigned long long v) {
    float lo, hi;
    asm("mov.b64 {%0, %1}, %2;" : "=f"(lo), "=f"(hi) : "l"(v));
    return lo + hi;
}

// ---------------------------------------------------------------------------
// k_pack: Wq|Wk|Wv|Wqp|Wkp|Wvp -> g_wcat[384][1152]
// ---------------------------------------------------------------------------
__global__ __launch_bounds__(256) void k_pack(
    const float* __restrict__ Wq, const float* __restrict__ Wk, const float* __restrict__ Wv,
    const float* __restrict__ Wqp, const float* __restrict__ Wkp, const float* __restrict__ Wvp)
{
    const int idx = blockIdx.x*256 + threadIdx.x;
    const int si = idx / PROJ_W, col = idx % PROJ_W;
    float v;
    if      (col < 192) v = Wq [si*192 + col];
    else if (col < 384) v = Wk [si*192 + col - 192];
    else if (col < 576) v = Wv [si*192 + col - 384];
    else if (col < 720) v = Wqp[si*144 + col - 576];
    else if (col < 864) v = Wkp[si*144 + col - 720];
    else                v = Wvp[si*288 + col - 864];
    g_wcat[idx] = v;
}

// ---------------------------------------------------------------------------
// Generic tiled fp32 GEMM
// ---------------------------------------------------------------------------
template<int BM, int BN, int TM, int TN>
__global__ __launch_bounds__(256) void k_gemm(
    const float* __restrict__ A, int lda,
    const float* __restrict__ B, int ldb,
    float* __restrict__ C, int ldc, int K)
{
    constexpr int BK = 32;
    __shared__ float As[BK][BM + 1];
    __shared__ __align__(16) float Bs[BK][BN];
    const int tid = threadIdx.x;
    const int ncols = BN / TN;
    const int tr = tid / ncols;
    const int tc = tid % ncols;
    const int m0 = blockIdx.y * BM;
    const int n0 = blockIdx.x * BN;

    float acc[TM][TN];
    #pragma unroll
    for (int i = 0; i < TM; i++)
        #pragma unroll
        for (int j = 0; j < TN; j++) acc[i][j] = 0.f;

    for (int k0 = 0; k0 < K; k0 += BK) {
        #pragma unroll
        for (int r = 0; r < (BM*BK)/256; r++) {
            const int idx = tid + r*256;
            const int m = idx / BK, kk = idx % BK;
            As[kk][m] = A[(m0 + m)*lda + k0 + kk];
        }
        #pragma unroll
        for (int r = 0; r < (BN*BK)/256; r++) {
            const int idx = tid + r*256;
            const int kk = idx / BN, n = idx % BN;
            Bs[kk][n] = B[(k0 + kk)*ldb + n0 + n];
        }
        __syncthreads();
        #pragma unroll
        for (int kk = 0; kk < BK; kk++) {
            float a[TM];
            #pragma unroll
            for (int i = 0; i < TM; i++) a[i] = As[kk][tr*TM + i];
            const float4 b4 = *(const float4*)&Bs[kk][tc*TN];
            #pragma unroll
            for (int i = 0; i < TM; i++) {
                acc[i][0] = fmaf(a[i], b4.x, acc[i][0]);
                acc[i][1] = fmaf(a[i], b4.y, acc[i][1]);
                acc[i][2] = fmaf(a[i], b4.z, acc[i][2]);
                acc[i][3] = fmaf(a[i], b4.w, acc[i][3]);
            }
        }
        __syncthreads();
    }
    #pragma unroll
    for (int i = 0; i < TM; i++) {
        float4 v = make_float4(acc[i][0], acc[i][1], acc[i][2], acc[i][3]);
        *(float4*)&C[(m0 + tr*TM + i)*ldc + n0 + tc*TN] = v;
    }
}

// ---------------------------------------------------------------------------
// k_projpost: frame transforms + point norms. One block per (b,n).
// ---------------------------------------------------------------------------
__global__ __launch_bounds__(128) void k_projpost(
    const float* __restrict__ R, const float* __restrict__ t)
{
    __shared__ float qq_sh[HH], kk_sh[HH];
    __shared__ float Rl[9], tl[3];
    const int bn  = blockIdx.x;
    const int tid = threadIdx.x;
    const float* proj = g_proj + bn*PROJ_W;

    if (tid < HH) { qq_sh[tid] = 0.f; kk_sh[tid] = 0.f; }
    if (tid < 9)  Rl[tid] = R[bn*9 + tid];
    if (tid < 3)  tl[tid] = t[bn*3 + tid];
    __syncthreads();

    for (int i = tid; i < HC; i += 128) {
        g_q[bn*HC + i] = proj[i];
        g_k[bn*HC + i] = proj[192 + i];
        g_v[bn*HC + i] = proj[384 + i];
    }
    if (tid < 96) {
        const int which = tid / 48;
        const int pt    = tid % 48;
        const int off   = which ? 720 : 576;
        const float px = proj[off + pt*3], py = proj[off + pt*3 + 1], pz = proj[off + pt*3 + 2];
        const float gx = Rl[0]*px + Rl[1]*py + Rl[2]*pz + tl[0];
        const float gy = Rl[3]*px + Rl[4]*py + Rl[5]*pz + tl[1];
        const float gz = Rl[6]*px + Rl[7]*py + Rl[8]*pz + tl[2];
        float* dst = (which ? g_kp : g_qp) + bn*HPQ3 + pt*3;
        dst[0] = gx; dst[1] = gy; dst[2] = gz;
        atomicAdd((which ? kk_sh : qq_sh) + pt/PQn, gx*gx + gy*gy + gz*gz);
    }
    if (tid < 96) {
        const int pt = tid;
        const float px = proj[864 + pt*3], py = proj[864 + pt*3 + 1], pz = proj[864 + pt*3 + 2];
        float* dst = g_vp + bn*HPV3 + pt*3;
        dst[0] = Rl[0]*px + Rl[1]*py + Rl[2]*pz + tl[0];
        dst[1] = Rl[3]*px + Rl[4]*py + Rl[5]*pz + tl[1];
        dst[2] = Rl[6]*px + Rl[7]*py + Rl[8]*pz + tl[2];
    }
    __syncthreads();
    if (tid < HH) { g_qq[bn*HH + tid] = qq_sh[tid]; g_kk[bn*HH + tid] = kk_sh[tid]; }
}

// ---------------------------------------------------------------------------
// k_bias: g_att[b,i,h,j] = sum_c z[b,i,j,c] * Wb[c,h].  z stream #1.
// 64 flattened rows per block; smem staged (132-padded rows, 16B-aligned).
// ---------------------------------------------------------------------------
#define BT_ROWS 64
__global__ __launch_bounds__(256) void k_bias(
    const float* __restrict__ z, const float* __restrict__ Wb)
{
    __shared__ __align__(16) float z_s[BT_ROWS*132];
    __shared__ __align__(16) float wb_s[HH*ZC];   // wb_s[h*128+c]
    const int tid = threadIdx.x;
    const int r0  = blockIdx.x * BT_ROWS;         // flattened (b*N+i)*N+j row

    for (int idx = tid; idx < HH*ZC; idx += 256) {
        const int c = idx / HH, h = idx % HH;
        wb_s[h*ZC + c] = Wb[idx];
    }
    // stage 64 z rows (coalesced float4 loads; 132-float padded rows)
    for (int idx = tid; idx < BT_ROWS*ZC/4; idx += 256) {
        const int r = idx >> 5, c4 = idx & 31;
        *(float4*)(z_s + r*132 + c4*4) = *(const float4*)(z + (size_t)r0*ZC + (size_t)idx*4);
    }
    __syncthreads();

    const int hg = tid >> 6;          // 0..3, 3 heads each
    const int r  = tid & 63;
    unsigned long long acc2[3] = {0ull, 0ull, 0ull};
    const float* zr = z_s + r*132;
    #pragma unroll 8
    for (int c4 = 0; c4 < 32; c4++) {
        const float4 zv = *(const float4*)(zr + c4*4);
        const unsigned long long zp0 = pack2(zv.x, zv.y);
        const unsigned long long zp1 = pack2(zv.z, zv.w);
        #pragma unroll
        for (int hh = 0; hh < 3; hh++) {
            const float4 wv = *(const float4*)(wb_s + (hg*3 + hh)*ZC + c4*4);
            ffma2(acc2[hh], zp0, pack2(wv.x, wv.y));
            ffma2(acc2[hh], zp1, pack2(wv.z, wv.w));
        }
    }
    const int row = r0 + r;
    const int b = row >> 18, rem = row & 262143;
    const int i = rem >> 9,  j   = rem & 511;
    float* dst = g_att + ((size_t)(b*NN + i)*HH + hg*3)*NN + j;
    #pragma unroll
    for (int hh = 0; hh < 3; hh++) dst[(size_t)hh*NN] = hadd2(acc2[hh]);
}

// ---------------------------------------------------------------------------
// k_logits: logits = WLC*(scal+bias) - coef*gamma*dist2; softmax; a -> g_att.
// One block = 4 query rows, 512 threads.
// ---------------------------------------------------------------------------
#define L_LOGITS 0                 /* 4*12*512 = 24576 */
#define L_QS     24576             /* 768 */
#define L_QPS    25344             /* 768 */
#define L_QQS    26112             /* 48 */
#define L_GM     26160             /* 12 */
#define LOG_SMEM_FLOATS 26172
#define LOG_SMEM_BYTES  (LOG_SMEM_FLOATS*4)

__global__ __launch_bounds__(512) void k_logits(const float* __restrict__ hw)
{
    extern __shared__ __align__(16) float sm[];
    float* logits = sm + L_LOGITS;
    float* q_s    = sm + L_QS;
    float* qp_s   = sm + L_QPS;
    float* qq_s   = sm + L_QQS;
    float* gm     = sm + L_GM;

    const int tid = threadIdx.x;
    const int blk = blockIdx.x;
    const int b   = blk >> 7;
    const int i0  = (blk & 127) << 2;

    // init logits with bias (coalesced, same layout)
    {
        float4* dst = (float4*)logits;
        const float4* src = (const float4*)(g_att + (size_t)(b*NN + i0)*HH*NN);
        #pragma unroll
        for (int r = 0; r < 12; r++) dst[tid + r*512] = src[tid + r*512];
    }
    for (int idx = tid; idx < 4*HC; idx += 512) {
        const int il = idx / HC;
        q_s[idx] = g_q[(b*NN + i0 + il)*HC + (idx % HC)];
    }
    for (int idx = tid; idx < 4*HPQ3; idx += 512) {
        const int il = idx / HPQ3, r = idx % HPQ3;
        const int h = r / 12, d = r % 12;
        qp_s[il*192 + h*16 + d] = g_qp[(b*NN + i0 + il)*HPQ3 + r];
    }
    if (tid < 48) qq_s[tid] = g_qq[(b*NN + i0 + tid/12)*HH + tid%12];
    if (tid < HH) gm[tid]   = log1pf(expf(hw[tid]));
    __syncthreads();

    const int j = tid;

    // scalar + point logits
    {
        const float4* kr  = (const float4*)(g_k  + (b*NN + j)*HC);
        const float4* kpr = (const float4*)(g_kp + (b*NN + j)*HPQ3);
        const float*  kkr = g_kk + (b*NN + j)*HH;
        for (int h = 0; h < HH; h++) {
            const float4 kv0 = kr[h*4+0], kv1 = kr[h*4+1], kv2 = kr[h*4+2], kv3 = kr[h*4+3];
            const float4 kp0 = kpr[h*3+0], kp1 = kpr[h*3+1], kp2 = kpr[h*3+2];
            const float  kkh = kkr[h];
            const float  gch = COEF * gm[h];
            #pragma unroll
            for (int il = 0; il < 4; il++) {
                const float4* qh  = (const float4*)(q_s  + il*192 + h*16);
                const float4* qph = (const float4*)(qp_s + il*192 + h*16);
                float sc = dot4(qh[0],kv0) + dot4(qh[1],kv1) + dot4(qh[2],kv2) + dot4(qh[3],kv3);
                float qk = dot4(qph[0],kp0) + dot4(qph[1],kp1) + dot4(qph[2],kp2);
                const float d2 = qq_s[il*HH + h] + kkh - 2.f*qk;
                const int   li = (il*HH + h)*NN + j;
                logits[li] = WLC*(sc*0.25f + logits[li]) - gch*d2;
            }
        }
    }
    __syncthreads();

    // softmax per (il,h) row
    {
        const int wid = tid >> 5, lane = tid & 31;
        for (int row = wid; row < 48; row += 16) {
            float* Lr = logits + row*NN;
            float m = -1e30f;
            for (int c = lane; c < NN; c += 32) m = fmaxf(m, Lr[c]);
            #pragma unroll
            for (int o = 16; o; o >>= 1) m = fmaxf(m, __shfl_xor_sync(0xffffffffu, m, o));
            float ssum = 0.f;
            for (int c = lane; c < NN; c += 32) { const float e = __expf(Lr[c] - m); Lr[c] = e; ssum += e; }
            #pragma unroll
            for (int o = 16; o; o >>= 1) ssum += __shfl_xor_sync(0xffffffffu, ssum, o);
            const float inv = 1.f / ssum;
            for (int c = lane; c < NN; c += 32) Lr[c] *= inv;
        }
    }
    __syncthreads();

    // write attention weights back (coalesced)
    {
        const float4* src = (const float4*)logits;
        float4* dst = (float4*)(g_att + (size_t)(b*NN + i0)*HH*NN);
        #pragma unroll
        for (int r = 0; r < 12; r++) dst[tid + r*512] = src[tid + r*512];
    }
}

// ---------------------------------------------------------------------------
// k_ofin: per (b,i): opair = a@z (z stream #2, 4-way j split),
//         o = a@v, opt_g = a@vp (4-way j split), frame transform + norms.
// smem: a_s[6144] part[6144] og[288] R_s[9] t_s[3] vpart[1920]
// ---------------------------------------------------------------------------
#define F_AS    0            /* 12*512 = 6144 */
#define F_PART  6144         /* 4*12*128 = 6144 */
#define F_OG    12288        /* 288 */
#define F_RS    12576        /* 9 */
#define F_TS    12585        /* 3 */
#define F_VPART 12588        /* 4*120*4 = 1920 (16B aligned: 12588%4==0) */
#define FIN_SMEM_FLOATS 14508
#define FIN_SMEM_BYTES  (FIN_SMEM_FLOATS*4)

__global__ __launch_bounds__(512) void k_ofin(
    const float* __restrict__ z, const float* __restrict__ R,
    const float* __restrict__ t)
{
    extern __shared__ __align__(16) float sm[];
    float* a_s   = sm + F_AS;
    float* part  = sm + F_PART;
    float* og    = sm + F_OG;
    float* R_s   = sm + F_RS;
    float* t_s   = sm + F_TS;
    float* vpart = sm + F_VPART;

    const int tid = threadIdx.x;
    const int blk = blockIdx.x;
    const int b   = blk >> 9;
    const int i   = blk & 511;

    // load a[i] (12x512) coalesced
    {
        float4* dst = (float4*)a_s;
        const float4* src = (const float4*)(g_att + (size_t)(b*NN + i)*HH*NN);
        #pragma unroll
        for (int r = 0; r < 3; r++) dst[tid + r*512] = src[tid + r*512];
    }
    if (tid < 9) R_s[tid] = R[(b*NN + i)*9 + tid];
    if (tid < 3) t_s[tid] = t[(b*NN + i)*3 + tid];
    __syncthreads();

    // ---- phase 1: opair partials: thread = (jquarter q, col) ----
    {
        const int q   = tid >> 7;
        const int col = tid & 127;
        unsigned long long acc2[HH];
        #pragma unroll
        for (int h = 0; h < HH; h++) acc2[h] = 0ull;
        const float* zb = z + ((size_t)(b*NN + i)*NN + q*128)*ZC + col;
        const float* ab = a_s + q*128;
        #pragma unroll 4
        for (int jj = 0; jj < 128; jj += 2) {
            const float z0 = zb[(size_t)jj*ZC];
            const float z1 = zb[(size_t)(jj+1)*ZC];
            const unsigned long long zp = pack2(z0, z1);
            #pragma unroll
            for (int h = 0; h < HH; h++) {
                const float2 af = *(const float2*)(ab + h*NN + jj);
                ffma2(acc2[h], pack2(af.x, af.y), zp);
            }
        }
        #pragma unroll
        for (int h = 0; h < HH; h++) part[(q*HH + h)*128 + col] = hadd2(acc2[h]);
    }

    // ---- phase 2: o/opt partials: thread = (jquarter q<4, col c<120) ----
    if (tid < 480) {
        const int q = tid / 120;
        const int c = tid % 120;
        const float* src; int ld, h;
        if (c < 48) { src = g_v  + (size_t)b*NN*HC   + c*4;      ld = HC;   h = c >> 2; }
        else        { src = g_vp + (size_t)b*NN*HPV3 + (c-48)*4; ld = HPV3; h = (c-48) / 6; }
        const float* arow = a_s + h*NN + q*128;
        const float* srcq = src + (size_t)(q*128)*ld;
        float4 acc = make_float4(0.f, 0.f, 0.f, 0.f);
        #pragma unroll 2
        for (int jj4 = 0; jj4 < 32; jj4++) {
            const float4 a4 = *(const float4*)(arow + jj4*4);
            const float4 v0 = *(const float4*)(srcq + (size_t)(jj4*4+0)*ld);
            const float4 v1 = *(const float4*)(srcq + (size_t)(jj4*4+1)*ld);
            const float4 v2 = *(const float4*)(srcq + (size_t)(jj4*4+2)*ld);
            const float4 v3 = *(const float4*)(srcq + (size_t)(jj4*4+3)*ld);
            acc.x = fmaf(a4.x, v0.x, fmaf(a4.y, v1.x, fmaf(a4.z, v2.x, fmaf(a4.w, v3.x, acc.x))));
            acc.y = fmaf(a4.x, v0.y, fmaf(a4.y, v1.y, fmaf(a4.z, v2.y, fmaf(a4.w, v3.y, acc.y))));
            acc.z = fmaf(a4.x, v0.z, fmaf(a4.y, v1.z, fmaf(a4.z, v2.z, fmaf(a4.w, v3.z, acc.z))));
            acc.w = fmaf(a4.x, v0.w, fmaf(a4.y, v1.w, fmaf(a4.z, v2.w, fmaf(a4.w, v3.w, acc.w))));
        }
        *(float4*)(vpart + (q*120 + c)*4) = acc;
    }
    __syncthreads();

    // ---- phase 3a: opair reduce (4 partials) ----
    for (int idx = tid; idx < HH*128; idx += 512) {
        const float s = part[idx] + part[1536 + idx] + part[2*1536 + idx] + part[3*1536 + idx];
        g_cat[(size_t)(b*NN + i)*CATW + 576 + idx] = s;
    }

    // ---- phase 3b: o/opt reduce (4 partials) ----
    if (tid < 120) {
        const float4 p0 = *(const float4*)(vpart + (0*120 + tid)*4);
        const float4 p1 = *(const float4*)(vpart + (1*120 + tid)*4);
        const float4 p2 = *(const float4*)(vpart + (2*120 + tid)*4);
        const float4 p3 = *(const float4*)(vpart + (3*120 + tid)*4);
        float4 s;
        s.x = (p0.x + p1.x) + (p2.x + p3.x);
        s.y = (p0.y + p1.y) + (p2.y + p3.y);
        s.z = (p0.z + p1.z) + (p2.z + p3.z);
        s.w = (p0.w + p1.w) + (p2.w + p3.w);
        if (tid < 48) *(float4*)(g_cat + (size_t)(b*NN + i)*CATW + tid*4) = s;
        else          *(float4*)(og + (tid - 48)*4) = s;
    }
    __syncthreads();

    // ---- phase 4: frame transform + norms ----
    if (tid < 96) {
        const int hp = tid;
        const float dx = og[hp*3 + 0] - t_s[0];
        const float dy = og[hp*3 + 1] - t_s[1];
        const float dz = og[hp*3 + 2] - t_s[2];
        const float ox = R_s[0]*dx + R_s[3]*dy + R_s[6]*dz;
        const float oy = R_s[1]*dx + R_s[4]*dy + R_s[7]*dz;
        const float oz = R_s[2]*dx + R_s[5]*dy + R_s[8]*dz;
        float* cg = g_cat + (size_t)(b*NN + i)*CATW;
        cg[192 + hp*3 + 0] = ox;
        cg[192 + hp*3 + 1] = oy;
        cg[192 + hp*3 + 2] = oz;
        cg[480 + hp] = sqrtf(ox*ox + oy*oy + oz*oz + 1e-8f);
    }
}

// ---------------------------------------------------------------------------
extern "C" void kernel_launch(void* const* d_in, const int* in_sizes, int n_in,
                              void* d_out, int out_size)
{
    const float* s    = (const float*)d_in[0];
    const float* z    = (const float*)d_in[1];
    const float* R    = (const float*)d_in[2];
    const float* t    = (const float*)d_in[3];
    const float* Wq   = (const float*)d_in[4];
    const float* Wk   = (const float*)d_in[5];
    const float* Wv   = (const float*)d_in[6];
    const float* Wqp  = (const float*)d_in[7];
    const float* Wkp  = (const float*)d_in[8];
    const float* Wvp  = (const float*)d_in[9];
    const float* Wb   = (const float*)d_in[10];
    const float* hw   = (const float*)d_in[11];
    const float* Wout = (const float*)d_in[12];
    float* out = (float*)d_out;

    cudaFuncSetAttribute(k_logits, cudaFuncAttributeMaxDynamicSharedMemorySize, LOG_SMEM_BYTES);
    cudaFuncSetAttribute(k_ofin,   cudaFuncAttributeMaxDynamicSharedMemorySize, FIN_SMEM_BYTES);

    float* g_wcat_p;  cudaGetSymbolAddress((void**)&g_wcat_p, g_wcat);
    float* g_proj_p;  cudaGetSymbolAddress((void**)&g_proj_p, g_proj);
    float* g_cat_p;   cudaGetSymbolAddress((void**)&g_cat_p,  g_cat);

    // bias = z @ Wb  (z stream #1, full-chip)
    k_bias<<<(BB*NN*NN)/BT_ROWS, 256>>>(z, Wb);

    // projections
    k_pack<<<(SS*PROJ_W)/256, 256>>>(Wq, Wk, Wv, Wqp, Wkp, Wvp);
    {
        dim3 grid(PROJ_W/64, (BB*NN)/64);
        k_gemm<64, 64, 4, 4><<<grid, 256>>>(s, SS, g_wcat_p, PROJ_W, g_proj_p, PROJ_W, SS);
    }
    k_projpost<<<BB*NN, 128>>>(R, t);

    // logits + softmax (bias in, attention weights out; both in g_att)
    k_logits<<<BB*(NN/4), 512, LOG_SMEM_BYTES>>>(hw);

    // opair + o + opt (z stream #2, full-chip)
    k_ofin<<<BB*NN, 512, FIN_SMEM_BYTES>>>(z, R, t);

    // out = g_cat[1024,2112] @ Wout[2112,384]
    {
        dim3 grid(SS/64, (BB*NN)/32);
        k_gemm<32, 64, 2, 4><<<grid, 256>>>(g_cat_p, CATW, Wout, SS, out, SS, CATW);
    }
}